// round 9
// baseline (speedup 1.0000x reference)
#include <cuda_runtime.h>
#include <math.h>

#define T_STEPS 1000
#define BATCH   16
#define MEL     80
#define HID     512
#define NCLS    64
#define NROWS   (T_STEPS*BATCH)      // 16000

#define NGROUPS   8
#define GCTAS     16                 // CTAs per cluster (sync domain)
#define SCAN_CTAS (NGROUPS*GCTAS)    // 128
#define GCOLS     32                 // cols per CTA
#define WSL       20                 // padded k-slice stride (16 data + 4 pad floats)

// ---------------- scratch (device globals; no allocation allowed) ----------
__device__ float g_be0[NROWS*HID];
__device__ float g_xn1[NROWS*HID];
__device__ float g_be1[NROWS*HID];
__device__ float g_hall[NROWS*HID];
__device__ float g_scale1[NROWS];

__device__ __forceinline__ float clip1(float v) {
    return fminf(fmaxf(v, -1.f), 1.f);
}

// ---------------- fused: xnorm0 + be0 GEMM ---------------------------------
__global__ __launch_bounds__(256) void fused_be0_kernel(
    const float* __restrict__ feats, const float* __restrict__ B0)
{
    __shared__ float xs[64][80];

    const int tid  = threadIdx.x;
    const int warp = tid >> 5, lane = tid & 31;
    const int r_base = blockIdx.x*64 + warp*8;

    #pragma unroll
    for (int rr = 0; rr < 8; rr++) {
        int r = r_base + rr;
        int t = r >> 4, b = r & 15;
        const float* row = feats + ((size_t)b*T_STEPS + t)*MEL;
        float v0 = row[lane];
        float v1 = row[lane+32];
        float v2 = (lane < 16) ? row[lane+64] : 0.f;
        float s = v0*v0 + v1*v1 + v2*v2;
        #pragma unroll
        for (int off = 16; off; off >>= 1) s += __shfl_xor_sync(0xffffffffu, s, off);
        float inv = 1.f/fmaxf(sqrtf(s), 1e-6f);
        int lr = warp*8 + rr;
        xs[lr][lane]    = clip1(v0*inv);
        xs[lr][lane+32] = clip1(v1*inv);
        if (lane < 16) xs[lr][lane+64] = clip1(v2*inv);
    }
    __syncwarp();

    #pragma unroll 1
    for (int q = 0; q < 4; q++) {
        int c0 = q*128 + lane*4;
        float acc[8][4];
        #pragma unroll
        for (int rr = 0; rr < 8; rr++)
            #pragma unroll
            for (int j = 0; j < 4; j++) acc[rr][j] = 0.f;

        for (int kc = 0; kc < 20; kc++) {
            float4 b40 = *(const float4*)(B0 + (size_t)(c0+0)*MEL + kc*4);
            float4 b41 = *(const float4*)(B0 + (size_t)(c0+1)*MEL + kc*4);
            float4 b42 = *(const float4*)(B0 + (size_t)(c0+2)*MEL + kc*4);
            float4 b43 = *(const float4*)(B0 + (size_t)(c0+3)*MEL + kc*4);
            #pragma unroll
            for (int rr = 0; rr < 8; rr++) {
                float4 x4 = *(const float4*)&xs[warp*8+rr][kc*4];
                acc[rr][0] += x4.x*b40.x + x4.y*b40.y + x4.z*b40.z + x4.w*b40.w;
                acc[rr][1] += x4.x*b41.x + x4.y*b41.y + x4.z*b41.z + x4.w*b41.w;
                acc[rr][2] += x4.x*b42.x + x4.y*b42.y + x4.z*b42.z + x4.w*b42.w;
                acc[rr][3] += x4.x*b43.x + x4.y*b43.y + x4.z*b43.z + x4.w*b43.w;
            }
        }
        #pragma unroll
        for (int rr = 0; rr < 8; rr++) {
            int r = r_base + rr;
            *(float4*)&g_be0[(size_t)r*HID + c0] =
                make_float4(acc[rr][0], acc[rr][1], acc[rr][2], acc[rr][3]);
        }
    }
}

// ---------------- x_norm + scale for cell1 input (be0) ---------------------
__global__ void xnorm1_kernel() {
    int w    = (blockIdx.x*blockDim.x + threadIdx.x) >> 5;
    int lane = threadIdx.x & 31;
    if (w >= NROWS) return;
    const float4* row = (const float4*)(g_be0 + (size_t)w*HID);
    float4 v[4];
    float s = 0.f;
    #pragma unroll
    for (int i = 0; i < 4; i++) {
        v[i] = row[lane + 32*i];
        s += v[i].x*v[i].x + v[i].y*v[i].y + v[i].z*v[i].z + v[i].w*v[i].w;
    }
    #pragma unroll
    for (int off = 16; off; off >>= 1) s += __shfl_xor_sync(0xffffffffu, s, off);
    float sc = fmaxf(sqrtf(s), 1e-6f);
    if (lane == 0) g_scale1[w] = sc;
    float inv = 1.f/sc;
    float4* o = (float4*)(g_xn1 + (size_t)w*HID);
    #pragma unroll
    for (int i = 0; i < 4; i++) {
        float4 u = v[i];
        u.x = clip1(u.x*inv);
        u.y = clip1(u.y*inv);
        u.z = clip1(u.z*inv);
        u.w = clip1(u.w*inv);
        o[lane + 32*i] = u;
    }
}

// ---------------- generic tiled SGEMM: C = A(M,K) @ W(N,K)^T ---------------
__global__ __launch_bounds__(256) void sgemm_nt(
    const float* __restrict__ A, int lda,
    const float* __restrict__ W, int ldw,
    float*       __restrict__ C, int ldc,
    int K, int accumulate, const float* __restrict__ bias, int remap)
{
    __shared__ float As[16][64];
    __shared__ float Ws[16][64];
    int bm = blockIdx.y*64, bn = blockIdx.x*64;
    int tid = threadIdx.x;
    int lr  = tid >> 2;
    int kq  = (tid & 3)*4;
    int tx  = tid & 15, ty = tid >> 4;
    float acc[4][4];
    #pragma unroll
    for (int i=0;i<4;i++)
        #pragma unroll
        for (int j=0;j<4;j++) acc[i][j]=0.f;

    for (int k0 = 0; k0 < K; k0 += 16) {
        float4 av = *(const float4*)(A + (size_t)(bm+lr)*lda + k0 + kq);
        float4 wv = *(const float4*)(W + (size_t)(bn+lr)*ldw + k0 + kq);
        As[kq+0][lr]=av.x; As[kq+1][lr]=av.y; As[kq+2][lr]=av.z; As[kq+3][lr]=av.w;
        Ws[kq+0][lr]=wv.x; Ws[kq+1][lr]=wv.y; Ws[kq+2][lr]=wv.z; Ws[kq+3][lr]=wv.w;
        __syncthreads();
        #pragma unroll
        for (int k = 0; k < 16; k++) {
            float4 a4 = *(float4*)&As[k][ty*4];
            float4 w4 = *(float4*)&Ws[k][tx*4];
            float ar[4] = {a4.x, a4.y, a4.z, a4.w};
            float wr[4] = {w4.x, w4.y, w4.z, w4.w};
            #pragma unroll
            for (int i=0;i<4;i++)
                #pragma unroll
                for (int j=0;j<4;j++) acc[i][j] += ar[i]*wr[j];
        }
        __syncthreads();
    }
    #pragma unroll
    for (int i = 0; i < 4; i++) {
        int r = bm + ty*4 + i;
        int orow = remap ? ((r & 15)*T_STEPS + (r >> 4)) : r;
        #pragma unroll
        for (int j = 0; j < 4; j++) {
            int cidx = bn + tx*4 + j;
            float val = acc[i][j];
            if (bias) val += bias[cidx];
            float* p = C + (size_t)orow*ldc + cidx;
            if (accumulate) val += *p;
            *p = val;
        }
    }
}

// ---------------- cluster helpers -------------------------------------------
__device__ __forceinline__ unsigned smem_u32(const void* p) {
    unsigned a;
    asm("{ .reg .u64 t; cvta.to.shared.u64 t, %1; cvt.u32.u64 %0, t; }"
        : "=r"(a) : "l"(p));
    return a;
}
__device__ __forceinline__ unsigned mapa32(unsigned addr, unsigned rank) {
    unsigned r;
    asm("mapa.shared::cluster.u32 %0, %1, %2;" : "=r"(r) : "r"(addr), "r"(rank));
    return r;
}
__device__ __forceinline__ void st_cluster16(unsigned addr, float4 v) {
    asm volatile("st.shared::cluster.v4.f32 [%0], {%1,%2,%3,%4};"
                 :: "r"(addr), "f"(v.x), "f"(v.y), "f"(v.z), "f"(v.w) : "memory");
}
__device__ __forceinline__ void st_cluster8(unsigned addr, float a, float b) {
    asm volatile("st.shared::cluster.v2.f32 [%0], {%1,%2};"
                 :: "r"(addr), "f"(a), "f"(b) : "memory");
}
__device__ __forceinline__ void cluster_bar() {
    asm volatile("barrier.cluster.arrive.aligned;" ::: "memory");
    asm volatile("barrier.cluster.wait.aligned;"   ::: "memory");
}
__device__ __forceinline__ unsigned ctarank() {
    unsigned r; asm("mov.u32 %0, %%cluster_ctarank;" : "=r"(r)); return r;
}

// ---------------- persistent scan: 8 clusters x 16 CTAs, 2 rows/cluster ----
__global__ __launch_bounds__(256, 1) void scan_kernel(
    const float* __restrict__ C1, const float* __restrict__ W1,
    const float* __restrict__ a1, const float* __restrict__ taup,
    const float* __restrict__ gamp)
{
    extern __shared__ float sm[];
    float* wC    = sm;                      // 32*32*20 = 20480
    float* wW    = wC + GCOLS*32*WSL;       // 20480
    float* hb    = wW + GCOLS*32*WSL;       // 64*20 = 1280 (2 rows, padded slices)
    float* eb    = hb + 64*WSL;             // 1280
    float* est   = eb + 64*WSL;             // 64  err staging [row][c]
    float* hst   = est + 64;                // 64  h staging
    float* nbuf  = hst + 64;                // 32  [cta*2 + row] norm partials
    float* sga   = nbuf + 32;               // 32
    float* snp0  = sga + GCOLS;             // 8
    float* snp1  = snp0 + 8;                // 8

    const int tid = threadIdx.x;
    const unsigned cg = ctarank();          // CTA in cluster
    const int g   = blockIdx.x >> 4;        // group = batch pair
    const int mbase = (int)cg*GCOLS;        // col base in [0,512)
    const int b0 = g*2;

    // weights into padded conflict-free slice layout
    for (int idx = tid; idx < GCOLS*HID; idx += 256) {
        int m = idx >> 9, k = idx & 511;
        int sl = (m*32 + (k>>4))*WSL + (k&15);
        wC[sl] = C1[(size_t)(mbase+m)*HID + k];
        wW[sl] = W1[(size_t)(mbase+m)*HID + k];
    }
    if (tid < GCOLS) sga[tid] = 1.f/(1.f + expf(-a1[mbase+tid]));
    for (int i = tid; i < 64*WSL; i += 256) hb[i] = 0.f;   // h0 = 0
    const float tau = taup[0], gam = gamp[0];

    const int warp = tid >> 5, lane = tid & 31;
    const float* wc0 = &wC[((warp*4+0)*32 + lane)*WSL];
    const float* wc1 = &wC[((warp*4+1)*32 + lane)*WSL];
    const float* wc2 = &wC[((warp*4+2)*32 + lane)*WSL];
    const float* wc3 = &wC[((warp*4+3)*32 + lane)*WSL];
    const float* ww0 = &wW[((warp*4+0)*32 + lane)*WSL];
    const float* ww1 = &wW[((warp*4+1)*32 + lane)*WSL];
    const float* ww2 = &wW[((warp*4+2)*32 + lane)*WSL];
    const float* ww3 = &wW[((warp*4+3)*32 + lane)*WSL];
    const float* hs0 = &hb[(lane)*WSL];
    const float* hs1 = &hb[(32+lane)*WSL];
    const float* es0 = &eb[(lane)*WSL];
    const float* es1 = &eb[(32+lane)*WSL];

    const int cloc = warp*4 + (lane & 3);   // owner lane's col (lane<4)
    const int col  = mbase + cloc;
    const int hv0i = ((col >> 4))*WSL + (col & 15);
    const int hv1i = ((32 + (col >> 4)))*WSL + (col & 15);

    // DSMEM scatter targets (fixed per thread): peer = tid>>4, chunk j = tid&15
    const int peer = tid >> 4, j = tid & 15;
    const int jrow = j >> 3, jj = j & 7;
    const unsigned dbyte = ((unsigned)((jrow*32 + (int)cg*2 + (jj>>2))*WSL + (jj&3)*4))*4u;
    const unsigned eb_dst = mapa32(smem_u32(eb) + dbyte, peer);
    const unsigned hb_dst = mapa32(smem_u32(hb) + dbyte, peer);
    // norm scatter: warp0 lanes<16 send CTA partial pair to peer 'lane'
    const unsigned nb_dst = (tid < 16) ? mapa32(smem_u32(nbuf) + cg*8u, (unsigned)tid) : 0u;

    const float4* est4 = (const float4*)est;
    const float4* hst4 = (const float4*)hst;
    const float2* nb2  = (const float2*)nbuf;

    __syncthreads();
    cluster_bar();   // all CTAs initialized before any DSMEM traffic

    for (int t = 0; t < T_STEPS; ++t) {
        // per-step operand prefetch (owners only), overlaps with GEMM
        float pb00=0.f, pb01=0.f, pb10=0.f, pb11=0.f;
        if (lane < 4) {
            size_t r = ((size_t)t*BATCH + b0)*HID + col;
            pb00 = __ldcg(&g_be0[r]);
            pb01 = __ldcg(&g_be0[r + HID]);
            pb10 = __ldcg(&g_be1[r]);
            pb11 = __ldcg(&g_be1[r + HID]);
        }
        float psc0 = __ldcg(&g_scale1[t*BATCH + b0]);
        float psc1 = __ldcg(&g_scale1[t*BATCH + b0 + 1]);

        // ---- phase A: P = h @ C1^T (4 cols x 2 rows per warp, 32-way k) ----
        float a00=0,a01=0,a10=0,a11=0,a20=0,a21=0,a30=0,a31=0;
        #pragma unroll
        for (int i = 0; i < 4; i++) {
            float4 x0 = *(const float4*)&hs0[i*4];
            float4 x1 = *(const float4*)&hs1[i*4];
            float4 u0 = *(const float4*)&wc0[i*4];
            float4 u1 = *(const float4*)&wc1[i*4];
            float4 u2 = *(const float4*)&wc2[i*4];
            float4 u3 = *(const float4*)&wc3[i*4];
            a00 += u0.x*x0.x + u0.y*x0.y + u0.z*x0.z + u0.w*x0.w;
            a01 += u0.x*x1.x + u0.y*x1.y + u0.z*x1.z + u0.w*x1.w;
            a10 += u1.x*x0.x + u1.y*x0.y + u1.z*x0.z + u1.w*x0.w;
            a11 += u1.x*x1.x + u1.y*x1.y + u1.z*x1.z + u1.w*x1.w;
            a20 += u2.x*x0.x + u2.y*x0.y + u2.z*x0.z + u2.w*x0.w;
            a21 += u2.x*x1.x + u2.y*x1.y + u2.z*x1.z + u2.w*x1.w;
            a30 += u3.x*x0.x + u3.y*x0.y + u3.z*x0.z + u3.w*x0.w;
            a31 += u3.x*x1.x + u3.y*x1.y + u3.z*x1.z + u3.w*x1.w;
        }
        #pragma unroll
        for (int off = 16; off; off >>= 1) {
            a00 += __shfl_xor_sync(0xffffffffu, a00, off);
            a01 += __shfl_xor_sync(0xffffffffu, a01, off);
            a10 += __shfl_xor_sync(0xffffffffu, a10, off);
            a11 += __shfl_xor_sync(0xffffffffu, a11, off);
            a20 += __shfl_xor_sync(0xffffffffu, a20, off);
            a21 += __shfl_xor_sync(0xffffffffu, a21, off);
            a30 += __shfl_xor_sync(0xffffffffu, a30, off);
            a31 += __shfl_xor_sync(0xffffffffu, a31, off);
        }
        float e0 = 0.f, e1 = 0.f;
        if (lane < 4) {
            float p0 = a00, p1 = a01;
            if (lane == 1) { p0 = a10; p1 = a11; }
            if (lane == 2) { p0 = a20; p1 = a21; }
            if (lane == 3) { p0 = a30; p1 = a31; }
            e0 = pb00 - tanhf(p0)*psc0;
            e1 = pb01 - tanhf(p1)*psc1;
            est[cloc]      = e0;
            est[32 + cloc] = e1;
        }
        float s0 = e0*e0, s1 = e1*e1;
        s0 += __shfl_xor_sync(0xffffffffu, s0, 1);
        s0 += __shfl_xor_sync(0xffffffffu, s0, 2);
        s1 += __shfl_xor_sync(0xffffffffu, s1, 1);
        s1 += __shfl_xor_sync(0xffffffffu, s1, 2);
        if (lane == 0) { snp0[warp] = s0; snp1[warp] = s1; }
        __syncthreads();

        // scatter err chunk to peer; warp0 also broadcasts CTA norm partials
        st_cluster16(eb_dst, est4[j]);
        if (tid < 16) {
            float p0 = snp0[tid & 7], p1 = snp1[tid & 7];
            #pragma unroll
            for (int off = 4; off; off >>= 1) {
                p0 += __shfl_xor_sync(0x0000ffffu, p0, off);
                p1 += __shfl_xor_sync(0x0000ffffu, p1, off);
            }
            st_cluster8(nb_dst, p0, p1);
        }
        cluster_bar();

        // every warp reduces the 16 CTA norm partials (local smem, no sync)
        float nr0 = 0.f, nr1 = 0.f;
        {
            float2 v = (lane < 16) ? nb2[lane] : make_float2(0.f, 0.f);
            nr0 = v.x; nr1 = v.y;
            #pragma unroll
            for (int off = 8; off; off >>= 1) {
                nr0 += __shfl_xor_sync(0xffffffffu, nr0, off);
                nr1 += __shfl_xor_sync(0xffffffffu, nr1, off);
            }
        }

        // ---- phase B: E = err @ W1^T -> h update ----
        float b00=0,b01=0,b10=0,b11=0,b20=0,b21=0,b30=0,b31=0;
        #pragma unroll
        for (int i = 0; i < 4; i++) {
            float4 x0 = *(const float4*)&es0[i*4];
            float4 x1 = *(const float4*)&es1[i*4];
            float4 u0 = *(const float4*)&ww0[i*4];
            float4 u1 = *(const float4*)&ww1[i*4];
            float4 u2 = *(const float4*)&ww2[i*4];
            float4 u3 = *(const float4*)&ww3[i*4];
            b00 += u0.x*x0.x + u0.y*x0.y + u0.z*x0.z + u0.w*x0.w;
            b01 += u0.x*x1.x + u0.y*x1.y + u0.z*x1.z + u0.w*x1.w;
            b10 += u1.x*x0.x + u1.y*x0.y + u1.z*x0.z + u1.w*x0.w;
            b11 += u1.x*x1.x + u1.y*x1.y + u1.z*x1.z + u1.w*x1.w;
            b20 += u2.x*x0.x + u2.y*x0.y + u2.z*x0.z + u2.w*x0.w;
            b21 += u2.x*x1.x + u2.y*x1.y + u2.z*x1.z + u2.w*x1.w;
            b30 += u3.x*x0.x + u3.y*x0.y + u3.z*x0.z + u3.w*x0.w;
            b31 += u3.x*x1.x + u3.y*x1.y + u3.z*x1.z + u3.w*x1.w;
        }
        #pragma unroll
        for (int off = 16; off; off >>= 1) {
            b00 += __shfl_xor_sync(0xffffffffu, b00, off);
            b01 += __shfl_xor_sync(0xffffffffu, b01, off);
            b10 += __shfl_xor_sync(0xffffffffu, b10, off);
            b11 += __shfl_xor_sync(0xffffffffu, b11, off);
            b20 += __shfl_xor_sync(0xffffffffu, b20, off);
            b21 += __shfl_xor_sync(0xffffffffu, b21, off);
            b30 += __shfl_xor_sync(0xffffffffu, b30, off);
            b31 += __shfl_xor_sync(0xffffffffu, b31, off);
        }
        if (lane < 4) {
            float q0 = b00, q1 = b01;
            if (lane == 1) { q0 = b10; q1 = b11; }
            if (lane == 2) { q0 = b20; q1 = b21; }
            if (lane == 3) { q0 = b30; q1 = b31; }
            float rel0 = fminf(sqrtf(nr0)/psc0, 4.f);
            float rel1 = fminf(sqrtf(nr1)/psc1, 4.f);
            float sur0 = 1.f/(1.f + expf(-(rel0 - tau)/gam));
            float sur1 = 1.f/(1.f + expf(-(rel1 - tau)/gam));
            float hv0 = hb[hv0i];
            float hv1 = hb[hv1i];
            float ih0 = 0.2f*hv0 + 0.6f*pb10 + 0.2f*sur0*q0;
            float ih1 = 0.2f*hv1 + 0.6f*pb11 + 0.2f*sur1*q1;
            float sg  = sga[cloc];
            float gg0 = sur0*sg, gg1 = sur1*sg;
            float hn0 = hv0*(1.f - gg0) + tanhf(ih0)*gg0;
            float hn1 = hv1*(1.f - gg1) + tanhf(ih1)*gg1;
            size_t orow = ((size_t)t*BATCH + b0)*HID + col;
            g_hall[orow]       = hn0;     // for head GEMM (off critical path)
            g_hall[orow + HID] = hn1;
            hst[cloc]      = hn0;
            hst[32 + cloc] = hn1;
        }
        __syncthreads();

        // scatter new h chunk to peers' hb
        st_cluster16(hb_dst, hst4[j]);
        cluster_bar();
    }
}

// ---------------- launch ----------------------------------------------------
extern "C" void kernel_launch(void* const* d_in, const int* in_sizes, int n_in,
                              void* d_out, int out_size)
{
    const float* feats  = (const float*)d_in[0];
    const float* B0     = (const float*)d_in[2];
    const float* C1     = (const float*)d_in[7];
    const float* B1     = (const float*)d_in[8];
    const float* W1     = (const float*)d_in[9];
    const float* a1     = (const float*)d_in[10];
    const float* tau1   = (const float*)d_in[11];
    const float* gam1   = (const float*)d_in[12];
    const float* head_w = (const float*)d_in[13];
    const float* head_b = (const float*)d_in[14];
    float* out = (float*)d_out;

    float *p_xn1, *p_be1, *p_hall;
    cudaGetSymbolAddress((void**)&p_xn1,  g_xn1);
    cudaGetSymbolAddress((void**)&p_be1,  g_be1);
    cudaGetSymbolAddress((void**)&p_hall, g_hall);

    const int SCAN_SMEM = (2*GCOLS*32*WSL + 2*64*WSL + 64 + 64 + 32 + GCOLS + 16 + 32)*4;
    cudaFuncSetAttribute(scan_kernel, cudaFuncAttributeMaxDynamicSharedMemorySize, SCAN_SMEM);
    cudaFuncSetAttribute(scan_kernel, cudaFuncAttributeNonPortableClusterSizeAllowed, 1);

    // launch #0: fused xnorm0 + be0 GEMM
    fused_be0_kernel<<<NROWS/64, 256>>>(feats, B0);
    // launch #1
    xnorm1_kernel<<<(NROWS*32)/256, 256>>>();
    // launch #2: be1 = xn1 @ B1^T
    dim3 g1(HID/64, NROWS/64);
    sgemm_nt<<<g1, 256>>>(p_xn1, HID, B1, HID, p_be1, HID, HID, 0, nullptr, 0);

    // launch #3: the scan (ncu capture target), 8 clusters of 16 CTAs
    {
        cudaLaunchConfig_t cfg = {};
        cfg.gridDim  = dim3(SCAN_CTAS, 1, 1);
        cfg.blockDim = dim3(256, 1, 1);
        cfg.dynamicSmemBytes = SCAN_SMEM;
        cudaLaunchAttribute attrs[1];
        attrs[0].id = cudaLaunchAttributeClusterDimension;
        attrs[0].val.clusterDim = {GCTAS, 1, 1};
        cfg.attrs = attrs;
        cfg.numAttrs = 1;
        cudaLaunchKernelEx(&cfg, scan_kernel, C1, W1, a1, tau1, gam1);
    }

    // head
    dim3 gh(NCLS/64, NROWS/64);
    sgemm_nt<<<gh, 256>>>(p_hall, HID, head_w,       2*HID, out, NCLS, HID, 0, nullptr, 1);
    sgemm_nt<<<gh, 256>>>(p_be1,  HID, head_w + HID, 2*HID, out, NCLS, HID, 1, head_b, 1);
}

// round 11
// speedup vs baseline: 1.3169x; 1.3169x over previous
#include <cuda_runtime.h>
#include <math.h>

#define T_STEPS 1000
#define BATCH   16
#define MEL     80
#define HID     512
#define NCLS    64
#define NROWS   (T_STEPS*BATCH)      // 16000

#define NGROUPS   8
#define GCTAS     16                 // CTAs per group (sync domain)
#define SCAN_CTAS (NGROUPS*GCTAS)    // 128
#define GCOLS     32                 // cols per CTA
#define WSL       20                 // padded k-slice stride (16 data + 4 pad floats)

// ---------------- scratch (device globals; no allocation allowed) ----------
__device__ float    g_be0[NROWS*HID];
__device__ float    g_xn1[NROWS*HID];
__device__ float    g_be1[NROWS*HID];
__device__ float    g_hall[NROWS*HID];
__device__ float    g_scale1[NROWS];
__device__ float    g_err[BATCH*HID];
__device__ float    g_normp[BATCH*128];   // [b][cta_in_group*8 + warp]
__device__ float    g_hzero[BATCH*HID];
__device__ unsigned g_ctr2[NGROUPS*2048]; // per-group per-step counters

__device__ __forceinline__ float clip1(float v) {
    return fminf(fmaxf(v, -1.f), 1.f);
}

// ---------------- fused: zero scratch + xnorm0 + be0 GEMM ------------------
__global__ __launch_bounds__(256) void fused_be0_kernel(
    const float* __restrict__ feats, const float* __restrict__ B0)
{
    __shared__ float xs[64][80];

    const int tid  = threadIdx.x;
    const int warp = tid >> 5, lane = tid & 31;
    const int r_base = blockIdx.x*64 + warp*8;

    if (blockIdx.x == 0) {
        for (int i = tid; i < NGROUPS*2048; i += 256) g_ctr2[i] = 0u;
        for (int i = tid; i < BATCH*HID; i += 256) g_hzero[i] = 0.f;
    }

    #pragma unroll
    for (int rr = 0; rr < 8; rr++) {
        int r = r_base + rr;
        int t = r >> 4, b = r & 15;
        const float* row = feats + ((size_t)b*T_STEPS + t)*MEL;
        float v0 = row[lane];
        float v1 = row[lane+32];
        float v2 = (lane < 16) ? row[lane+64] : 0.f;
        float s = v0*v0 + v1*v1 + v2*v2;
        #pragma unroll
        for (int off = 16; off; off >>= 1) s += __shfl_xor_sync(0xffffffffu, s, off);
        float inv = 1.f/fmaxf(sqrtf(s), 1e-6f);
        int lr = warp*8 + rr;
        xs[lr][lane]    = clip1(v0*inv);
        xs[lr][lane+32] = clip1(v1*inv);
        if (lane < 16) xs[lr][lane+64] = clip1(v2*inv);
    }
    __syncwarp();

    #pragma unroll 1
    for (int q = 0; q < 4; q++) {
        int c0 = q*128 + lane*4;
        float acc[8][4];
        #pragma unroll
        for (int rr = 0; rr < 8; rr++)
            #pragma unroll
            for (int j = 0; j < 4; j++) acc[rr][j] = 0.f;

        for (int kc = 0; kc < 20; kc++) {
            float4 b40 = *(const float4*)(B0 + (size_t)(c0+0)*MEL + kc*4);
            float4 b41 = *(const float4*)(B0 + (size_t)(c0+1)*MEL + kc*4);
            float4 b42 = *(const float4*)(B0 + (size_t)(c0+2)*MEL + kc*4);
            float4 b43 = *(const float4*)(B0 + (size_t)(c0+3)*MEL + kc*4);
            #pragma unroll
            for (int rr = 0; rr < 8; rr++) {
                float4 x4 = *(const float4*)&xs[warp*8+rr][kc*4];
                acc[rr][0] += x4.x*b40.x + x4.y*b40.y + x4.z*b40.z + x4.w*b40.w;
                acc[rr][1] += x4.x*b41.x + x4.y*b41.y + x4.z*b41.z + x4.w*b41.w;
                acc[rr][2] += x4.x*b42.x + x4.y*b42.y + x4.z*b42.z + x4.w*b42.w;
                acc[rr][3] += x4.x*b43.x + x4.y*b43.y + x4.z*b43.z + x4.w*b43.w;
            }
        }
        #pragma unroll
        for (int rr = 0; rr < 8; rr++) {
            int r = r_base + rr;
            *(float4*)&g_be0[(size_t)r*HID + c0] =
                make_float4(acc[rr][0], acc[rr][1], acc[rr][2], acc[rr][3]);
        }
    }
}

// ---------------- x_norm + scale for cell1 input (be0) ---------------------
__global__ void xnorm1_kernel() {
    int w    = (blockIdx.x*blockDim.x + threadIdx.x) >> 5;
    int lane = threadIdx.x & 31;
    if (w >= NROWS) return;
    const float4* row = (const float4*)(g_be0 + (size_t)w*HID);
    float4 v[4];
    float s = 0.f;
    #pragma unroll
    for (int i = 0; i < 4; i++) {
        v[i] = row[lane + 32*i];
        s += v[i].x*v[i].x + v[i].y*v[i].y + v[i].z*v[i].z + v[i].w*v[i].w;
    }
    #pragma unroll
    for (int off = 16; off; off >>= 1) s += __shfl_xor_sync(0xffffffffu, s, off);
    float sc = fmaxf(sqrtf(s), 1e-6f);
    if (lane == 0) g_scale1[w] = sc;
    float inv = 1.f/sc;
    float4* o = (float4*)(g_xn1 + (size_t)w*HID);
    #pragma unroll
    for (int i = 0; i < 4; i++) {
        float4 u = v[i];
        u.x = clip1(u.x*inv);
        u.y = clip1(u.y*inv);
        u.z = clip1(u.z*inv);
        u.w = clip1(u.w*inv);
        o[lane + 32*i] = u;
    }
}

// ---------------- generic tiled SGEMM: C = A(M,K) @ W(N,K)^T ---------------
__global__ __launch_bounds__(256) void sgemm_nt(
    const float* __restrict__ A, int lda,
    const float* __restrict__ W, int ldw,
    float*       __restrict__ C, int ldc,
    int K, int accumulate, const float* __restrict__ bias, int remap)
{
    __shared__ float As[16][64];
    __shared__ float Ws[16][64];
    int bm = blockIdx.y*64, bn = blockIdx.x*64;
    int tid = threadIdx.x;
    int lr  = tid >> 2;
    int kq  = (tid & 3)*4;
    int tx  = tid & 15, ty = tid >> 4;
    float acc[4][4];
    #pragma unroll
    for (int i=0;i<4;i++)
        #pragma unroll
        for (int j=0;j<4;j++) acc[i][j]=0.f;

    for (int k0 = 0; k0 < K; k0 += 16) {
        float4 av = *(const float4*)(A + (size_t)(bm+lr)*lda + k0 + kq);
        float4 wv = *(const float4*)(W + (size_t)(bn+lr)*ldw + k0 + kq);
        As[kq+0][lr]=av.x; As[kq+1][lr]=av.y; As[kq+2][lr]=av.z; As[kq+3][lr]=av.w;
        Ws[kq+0][lr]=wv.x; Ws[kq+1][lr]=wv.y; Ws[kq+2][lr]=wv.z; Ws[kq+3][lr]=wv.w;
        __syncthreads();
        #pragma unroll
        for (int k = 0; k < 16; k++) {
            float4 a4 = *(float4*)&As[k][ty*4];
            float4 w4 = *(float4*)&Ws[k][tx*4];
            float ar[4] = {a4.x, a4.y, a4.z, a4.w};
            float wr[4] = {w4.x, w4.y, w4.z, w4.w};
            #pragma unroll
            for (int i=0;i<4;i++)
                #pragma unroll
                for (int j=0;j<4;j++) acc[i][j] += ar[i]*wr[j];
        }
        __syncthreads();
    }
    #pragma unroll
    for (int i = 0; i < 4; i++) {
        int r = bm + ty*4 + i;
        int orow = remap ? ((r & 15)*T_STEPS + (r >> 4)) : r;
        #pragma unroll
        for (int j = 0; j < 4; j++) {
            int cidx = bn + tx*4 + j;
            float val = acc[i][j];
            if (bias) val += bias[cidx];
            float* p = C + (size_t)orow*ldc + cidx;
            if (accumulate) val += *p;
            *p = val;
        }
    }
}

// ---------------- group barrier: 16 arrivals, release/acquire ---------------
__device__ __forceinline__ void gbar(unsigned* c) {
    __syncthreads();
    if (threadIdx.x == 0) {
        asm volatile("red.release.gpu.global.add.u32 [%0], 1;" :: "l"(c) : "memory");
        unsigned v;
        do {
            asm volatile("ld.acquire.gpu.global.u32 %0, [%1];" : "=r"(v) : "l"(c) : "memory");
        } while (v < GCTAS);
    }
    __syncthreads();
}

// ---------------- persistent scan: 8 groups x 16 CTAs, 2 batch rows/group ---
__global__ __launch_bounds__(256, 1) void scan_kernel(
    const float* __restrict__ C1, const float* __restrict__ W1,
    const float* __restrict__ a1, const float* __restrict__ taup,
    const float* __restrict__ gamp)
{
    extern __shared__ float sm[];
    float* wC   = sm;                       // 32*32*20 = 20480
    float* wW   = wC + GCOLS*32*WSL;        // 20480
    float* hb   = wW + GCOLS*32*WSL;        // 64*20 = 1280 (2 rows, padded slices)
    float* eb   = hb + 64*WSL;              // 1280
    float* sga  = eb + 64*WSL;              // 32
    float* snorm= sga + GCOLS;              // 2

    const int cta = blockIdx.x;
    const int g   = cta >> 4;               // group = batch pair
    const int cg  = cta & 15;               // CTA in group
    const int tid = threadIdx.x;
    const int mbase = cg*GCOLS;             // col base in [0,512)
    const int b0 = g*2;

    // weights into padded conflict-free slice layout: slice (m*32 + k/16), len 16
    for (int idx = tid; idx < GCOLS*HID; idx += 256) {
        int m = idx >> 9, k = idx & 511;
        int sl = (m*32 + (k>>4))*WSL + (k&15);
        wC[sl] = C1[(size_t)(mbase+m)*HID + k];
        wW[sl] = W1[(size_t)(mbase+m)*HID + k];
    }
    if (tid < GCOLS) sga[tid] = 1.f/(1.f + expf(-a1[mbase+tid]));
    const float tau = taup[0], gam = gamp[0];
    unsigned* ctr = g_ctr2 + g*2048;
    __syncthreads();

    const int warp = tid >> 5, lane = tid & 31;   // warp covers 4 cols, lane = k-slice
    const float* wc0 = &wC[((warp*4+0)*32 + lane)*WSL];
    const float* wc1 = &wC[((warp*4+1)*32 + lane)*WSL];
    const float* wc2 = &wC[((warp*4+2)*32 + lane)*WSL];
    const float* wc3 = &wC[((warp*4+3)*32 + lane)*WSL];
    const float* ww0 = &wW[((warp*4+0)*32 + lane)*WSL];
    const float* ww1 = &wW[((warp*4+1)*32 + lane)*WSL];
    const float* ww2 = &wW[((warp*4+2)*32 + lane)*WSL];
    const float* ww3 = &wW[((warp*4+3)*32 + lane)*WSL];
    const float* hs0 = &hb[(lane)*WSL];
    const float* hs1 = &hb[(32+lane)*WSL];
    const float* es0 = &eb[(lane)*WSL];
    const float* es1 = &eb[(32+lane)*WSL];

    const int cloc = warp*4 + (lane & 3);   // this lane's col (owners: lane<4)
    const int col  = mbase + cloc;
    const int hv0i = ((col >> 4))*WSL + (col & 15);       // row0 slice of h
    const int hv1i = ((32 + (col >> 4)))*WSL + (col & 15);

    // ---- preload step-0 operands (DRAM; consumed in phase A/B epilogues) ----
    float pb00=0.f, pb01=0.f, pb10=0.f, pb11=0.f;
    if (lane < 4) {
        size_t r = (size_t)b0*HID + col;
        pb00 = __ldcg(&g_be0[r]);
        pb01 = __ldcg(&g_be0[r + HID]);
        pb10 = __ldcg(&g_be1[r]);
        pb11 = __ldcg(&g_be1[r + HID]);
    }
    float psc0 = __ldcg(&g_scale1[b0]);
    float psc1 = __ldcg(&g_scale1[b0 + 1]);

    for (int t = 0; t < T_STEPS; ++t) {
        // load h (2 rows, 4KB) into padded smem
        {
            const float* src = (t == 0) ? (g_hzero + b0*HID)
                                        : (g_hall + ((size_t)(t-1)*BATCH + b0)*HID);
            float4 v = __ldcg(((const float4*)src) + tid);
            int row = tid >> 7, k4 = (tid & 127)*4;
            *(float4*)&hb[(row*32 + (k4>>4))*WSL + (k4&15)] = v;
        }
        __syncthreads();

        // ---- phase A: P = h @ C1^T (4 cols x 2 rows per warp, 32-way k-split)
        float a00=0,a01=0,a10=0,a11=0,a20=0,a21=0,a30=0,a31=0;
        #pragma unroll
        for (int i = 0; i < 4; i++) {
            float4 x0 = *(const float4*)&hs0[i*4];
            float4 x1 = *(const float4*)&hs1[i*4];
            float4 u0 = *(const float4*)&wc0[i*4];
            float4 u1 = *(const float4*)&wc1[i*4];
            float4 u2 = *(const float4*)&wc2[i*4];
            float4 u3 = *(const float4*)&wc3[i*4];
            a00 += u0.x*x0.x + u0.y*x0.y + u0.z*x0.z + u0.w*x0.w;
            a01 += u0.x*x1.x + u0.y*x1.y + u0.z*x1.z + u0.w*x1.w;
            a10 += u1.x*x0.x + u1.y*x0.y + u1.z*x0.z + u1.w*x0.w;
            a11 += u1.x*x1.x + u1.y*x1.y + u1.z*x1.z + u1.w*x1.w;
            a20 += u2.x*x0.x + u2.y*x0.y + u2.z*x0.z + u2.w*x0.w;
            a21 += u2.x*x1.x + u2.y*x1.y + u2.z*x1.z + u2.w*x1.w;
            a30 += u3.x*x0.x + u3.y*x0.y + u3.z*x0.z + u3.w*x0.w;
            a31 += u3.x*x1.x + u3.y*x1.y + u3.z*x1.z + u3.w*x1.w;
        }
        #pragma unroll
        for (int off = 16; off; off >>= 1) {
            a00 += __shfl_xor_sync(0xffffffffu, a00, off);
            a01 += __shfl_xor_sync(0xffffffffu, a01, off);
            a10 += __shfl_xor_sync(0xffffffffu, a10, off);
            a11 += __shfl_xor_sync(0xffffffffu, a11, off);
            a20 += __shfl_xor_sync(0xffffffffu, a20, off);
            a21 += __shfl_xor_sync(0xffffffffu, a21, off);
            a30 += __shfl_xor_sync(0xffffffffu, a30, off);
            a31 += __shfl_xor_sync(0xffffffffu, a31, off);
        }
        float e0 = 0.f, e1 = 0.f;
        if (lane < 4) {
            float p0 = a00, p1 = a01;
            if (lane == 1) { p0 = a10; p1 = a11; }
            if (lane == 2) { p0 = a20; p1 = a21; }
            if (lane == 3) { p0 = a30; p1 = a31; }
            e0 = pb00 - tanhf(p0)*psc0;
            e1 = pb01 - tanhf(p1)*psc1;
            g_err[b0*HID + col]     = e0;
            g_err[(b0+1)*HID + col] = e1;
        }
        float s0 = e0*e0, s1 = e1*e1;     // non-owners contribute 0
        #pragma unroll
        for (int off = 16; off; off >>= 1) {
            s0 += __shfl_xor_sync(0xffffffffu, s0, off);
            s1 += __shfl_xor_sync(0xffffffffu, s1, off);
        }
        if (lane == 0) {
            g_normp[b0*128     + cg*8 + warp] = s0;
            g_normp[(b0+1)*128 + cg*8 + warp] = s1;
        }
        gbar(ctr + 2*t);

        // ---- prefetch step t+1 operands (hidden under phase B + barrier) ---
        float npb00=0.f, npb01=0.f, npb10=0.f, npb11=0.f, npsc0, npsc1;
        {
            int tn = (t + 1 < T_STEPS) ? (t + 1) : t;
            if (lane < 4) {
                size_t r = ((size_t)tn*BATCH + b0)*HID + col;
                npb00 = __ldcg(&g_be0[r]);
                npb01 = __ldcg(&g_be0[r + HID]);
                npb10 = __ldcg(&g_be1[r]);
                npb11 = __ldcg(&g_be1[r + HID]);
            }
            npsc0 = __ldcg(&g_scale1[tn*BATCH + b0]);
            npsc1 = __ldcg(&g_scale1[tn*BATCH + b0 + 1]);
        }

        // load full error (2 rows) + reduce norm partials
        {
            float4 v = __ldcg(((const float4*)(g_err + b0*HID)) + tid);
            int row = tid >> 7, k4 = (tid & 127)*4;
            *(float4*)&eb[(row*32 + (k4>>4))*WSL + (k4&15)] = v;
        }
        if (warp < 2) {
            float4 v = __ldcg(((const float4*)(g_normp + (b0+warp)*128)) + lane);
            float s = v.x + v.y + v.z + v.w;
            #pragma unroll
            for (int off = 16; off; off >>= 1) s += __shfl_xor_sync(0xffffffffu, s, off);
            if (lane == 0) snorm[warp] = s;
        }
        __syncthreads();

        // ---- phase B: E = err @ W1^T -> h update ----
        float b00=0,b01=0,b10=0,b11=0,b20=0,b21=0,b30=0,b31=0;
        #pragma unroll
        for (int i = 0; i < 4; i++) {
            float4 x0 = *(const float4*)&es0[i*4];
            float4 x1 = *(const float4*)&es1[i*4];
            float4 u0 = *(const float4*)&ww0[i*4];
            float4 u1 = *(const float4*)&ww1[i*4];
            float4 u2 = *(const float4*)&ww2[i*4];
            float4 u3 = *(const float4*)&ww3[i*4];
            b00 += u0.x*x0.x + u0.y*x0.y + u0.z*x0.z + u0.w*x0.w;
            b01 += u0.x*x1.x + u0.y*x1.y + u0.z*x1.z + u0.w*x1.w;
            b10 += u1.x*x0.x + u1.y*x0.y + u1.z*x0.z + u1.w*x0.w;
            b11 += u1.x*x1.x + u1.y*x1.y + u1.z*x1.z + u1.w*x1.w;
            b20 += u2.x*x0.x + u2.y*x0.y + u2.z*x0.z + u2.w*x0.w;
            b21 += u2.x*x1.x + u2.y*x1.y + u2.z*x1.z + u2.w*x1.w;
            b30 += u3.x*x0.x + u3.y*x0.y + u3.z*x0.z + u3.w*x0.w;
            b31 += u3.x*x1.x + u3.y*x1.y + u3.z*x1.z + u3.w*x1.w;
        }
        #pragma unroll
        for (int off = 16; off; off >>= 1) {
            b00 += __shfl_xor_sync(0xffffffffu, b00, off);
            b01 += __shfl_xor_sync(0xffffffffu, b01, off);
            b10 += __shfl_xor_sync(0xffffffffu, b10, off);
            b11 += __shfl_xor_sync(0xffffffffu, b11, off);
            b20 += __shfl_xor_sync(0xffffffffu, b20, off);
            b21 += __shfl_xor_sync(0xffffffffu, b21, off);
            b30 += __shfl_xor_sync(0xffffffffu, b30, off);
            b31 += __shfl_xor_sync(0xffffffffu, b31, off);
        }
        if (lane < 4) {
            float q0 = b00, q1 = b01;
            if (lane == 1) { q0 = b10; q1 = b11; }
            if (lane == 2) { q0 = b20; q1 = b21; }
            if (lane == 3) { q0 = b30; q1 = b31; }
            float rel0 = fminf(sqrtf(snorm[0])/psc0, 4.f);
            float rel1 = fminf(sqrtf(snorm[1])/psc1, 4.f);
            float sur0 = 1.f/(1.f + expf(-(rel0 - tau)/gam));
            float sur1 = 1.f/(1.f + expf(-(rel1 - tau)/gam));
            float hv0 = hb[hv0i];
            float hv1 = hb[hv1i];
            float ih0 = 0.2f*hv0 + 0.6f*pb10 + 0.2f*sur0*q0;
            float ih1 = 0.2f*hv1 + 0.6f*pb11 + 0.2f*sur1*q1;
            float sg  = sga[cloc];
            float gg0 = sur0*sg, gg1 = sur1*sg;
            size_t orow = ((size_t)t*BATCH + b0)*HID + col;
            g_hall[orow]       = hv0*(1.f - gg0) + tanhf(ih0)*gg0;
            g_hall[orow + HID] = hv1*(1.f - gg1) + tanhf(ih1)*gg1;
        }
        gbar(ctr + 2*t + 1);

        // rotate prefetched operands into current
        pb00 = npb00; pb01 = npb01; pb10 = npb10; pb11 = npb11;
        psc0 = npsc0; psc1 = npsc1;
    }
}

// ---------------- launch ----------------------------------------------------
extern "C" void kernel_launch(void* const* d_in, const int* in_sizes, int n_in,
                              void* d_out, int out_size)
{
    const float* feats  = (const float*)d_in[0];
    const float* B0     = (const float*)d_in[2];
    const float* C1     = (const float*)d_in[7];
    const float* B1     = (const float*)d_in[8];
    const float* W1     = (const float*)d_in[9];
    const float* a1     = (const float*)d_in[10];
    const float* tau1   = (const float*)d_in[11];
    const float* gam1   = (const float*)d_in[12];
    const float* head_w = (const float*)d_in[13];
    const float* head_b = (const float*)d_in[14];
    float* out = (float*)d_out;

    float *p_xn1, *p_be1, *p_hall;
    cudaGetSymbolAddress((void**)&p_xn1,  g_xn1);
    cudaGetSymbolAddress((void**)&p_be1,  g_be1);
    cudaGetSymbolAddress((void**)&p_hall, g_hall);

    const int SCAN_SMEM = (2*GCOLS*32*WSL + 2*64*WSL + GCOLS + 2 + 30)*4;
    cudaFuncSetAttribute(scan_kernel, cudaFuncAttributeMaxDynamicSharedMemorySize, SCAN_SMEM);

    // launch #0: fused zero + xnorm0 + be0 GEMM
    fused_be0_kernel<<<NROWS/64, 256>>>(feats, B0);
    // launch #1
    xnorm1_kernel<<<(NROWS*32)/256, 256>>>();
    // launch #2: be1 = xn1 @ B1^T
    dim3 g1(HID/64, NROWS/64);
    sgemm_nt<<<g1, 256>>>(p_xn1, HID, B1, HID, p_be1, HID, HID, 0, nullptr, 0);
    // launch #3: the scan (ncu capture target)
    scan_kernel<<<SCAN_CTAS, 256, SCAN_SMEM>>>(C1, W1, a1, tau1, gam1);
    // head
    dim3 gh(NCLS/64, NROWS/64);
    sgemm_nt<<<gh, 256>>>(p_hall, HID, head_w,       2*HID, out, NCLS, HID, 0, nullptr, 1);
    sgemm_nt<<<gh, 256>>>(p_be1,  HID, head_w + HID, 2*HID, out, NCLS, HID, 1, head_b, 1);
}